// round 2
// baseline (speedup 1.0000x reference)
#include <cuda_runtime.h>

// ---------------------------------------------------------------------------
// 4-layer LSTM (B=128, T=1024, D=128, H=[100,100,200,200]) + dense head.
// Persistent-grid per-layer kernels: 128 co-resident CTAs, custom grid barrier
// per time step. Weights stationary in SMEM, c-state in registers, h exchanged
// through a small global ping-pong buffer.
// ---------------------------------------------------------------------------

#define TLEN 1024
#define BSZ  128
#define HPAD 256
#define NBLK 128
#define NTHR 256

// Scratch (static device allocations; no cudaMalloc allowed)
__device__ float g_seqA[BSZ * TLEN * 200];   // layer output sequences (ping)
__device__ float g_seqB[BSZ * TLEN * 200];   // layer output sequences (pong)
__device__ float g_hbuf[2 * BSZ * HPAD];     // per-step h double buffer
__device__ unsigned g_cnt = 0;
__device__ unsigned g_gen = 0;

__device__ __forceinline__ float sigm(float x) {
    return 1.0f / (1.0f + __expf(-x));
}

// Sense-reversing grid barrier for NBLK co-resident CTAs.
__device__ __forceinline__ void grid_sync() {
    __syncthreads();
    if (threadIdx.x == 0) {
        __threadfence();
        unsigned gen = *((volatile unsigned*)&g_gen);
        if (atomicAdd(&g_cnt, 1u) == (unsigned)(NBLK - 1)) {
            g_cnt = 0;
            __threadfence();
            atomicAdd(&g_gen, 1u);
        } else {
            while (*((volatile unsigned*)&g_gen) == gen) { __nanosleep(64); }
        }
        __threadfence();
    }
    __syncthreads();
}

// One LSTM layer over the full sequence.
// Block tile: RB batch rows x 16 h-cols (x4 gates). CJ col-groups, 128/RB row
// groups, NBLK blocks total. Threads: SPLIT k-groups of RB*4 threads; each
// thread accumulates a 1r x 4j x 4gate register tile; partials reduced in smem.
// XSEL: 2 = use Xarg, 0 = g_seqA, 1 = g_seqB. YSEL: 0 = g_seqA, 1 = g_seqB, 2 = none.
template <int DIN, int H, int RB, int CJ, int XSEL, int YSEL>
__global__ void __launch_bounds__(NTHR, 1)
lstm_layer(const float* __restrict__ Xarg,
           const float* __restrict__ Wx,
           const float* __restrict__ Wh,
           const float* __restrict__ bias)
{
    constexpr int K     = DIN + H;     // fused [x, h] depth
    constexpr int NH    = RB * 16;     // h elems per block
    constexpr int XS    = RB + 1;      // xh smem stride (bank-conflict pad)
    constexpr int GSZ   = RB * 4;      // threads per k-split group
    constexpr int SPLIT = NTHR / GSZ;  // k-split factor

    const float* X = (XSEL == 2) ? Xarg : (XSEL == 0 ? g_seqA : g_seqB);
    float*       Y = (YSEL == 0) ? g_seqA : (YSEL == 1 ? g_seqB : (float*)0);

    extern __shared__ float sm[];
    float* W_s  = sm;                  // [K][4 gates][16 j]  (K*64)
    float* xh_s = W_s + K * 64;        // [K][RB] (+pad)      (K*XS)
    float* b_s  = xh_s + K * XS;       // [64]
    float* zp   = b_s + 64;            // [SPLIT][4][NH]

    const int tid   = threadIdx.x;
    const int rbase = (blockIdx.x / CJ) * RB;
    const int jbase = (blockIdx.x % CJ) * 16;

    // ---- load stationary weights into smem (zero-padded beyond H) ----
    for (int idx = tid; idx < K * 64; idx += NTHR) {
        int k = idx >> 6, c = idx & 63, g = c >> 4, jj = c & 15;
        int j = jbase + jj;
        float v = 0.0f;
        if (j < H) v = (k < DIN) ? Wx[k * (4 * H) + g * H + j]
                                 : Wh[(k - DIN) * (4 * H) + g * H + j];
        W_s[idx] = v;
    }
    if (tid < 64) {
        int g = tid >> 4, jj = tid & 15, j = jbase + jj;
        b_s[tid] = (j < H) ? bias[g * H + j] : 0.0f;
    }
    // zero initial h for our (b, j) slice
    if (tid < NH) {
        int rr = tid >> 4, jj = tid & 15;
        g_hbuf[(rbase + rr) * HPAD + jbase + jj] = 0.0f;
    }
    float c_state = 0.0f;
    __syncthreads();
    grid_sync();  // initial h visible everywhere

    const int split = tid / GSZ;
    const int tg    = tid % GSZ;
    const int r     = tg >> 2;
    const int jq    = tg & 3;
    const int k0    = (split * K) / SPLIT;
    const int k1    = ((split + 1) * K) / SPLIT;

    for (int t = 0; t < TLEN; ++t) {
        const float* __restrict__ hprev = g_hbuf + (t & 1) * (BSZ * HPAD);
        float* __restrict__       hnext = g_hbuf + ((t + 1) & 1) * (BSZ * HPAD);

        // ---- stage xh tile [K][RB] into smem (transposed, coalesced gmem) ----
        for (int idx = tid; idx < RB * K; idx += NTHR) {
            int rr = idx / K;
            int k  = idx - rr * K;
            int b  = rbase + rr;
            float v = (k < DIN) ? X[(b * TLEN + t) * DIN + k]
                                : hprev[b * HPAD + (k - DIN)];
            xh_s[k * XS + rr] = v;
        }
        __syncthreads();

        // ---- register-tiled partial GEMM over [k0, k1) ----
        float acc[4][4];
        #pragma unroll
        for (int g = 0; g < 4; ++g)
            #pragma unroll
            for (int q = 0; q < 4; ++q) acc[g][q] = 0.0f;

        const float*  xp = xh_s + k0 * XS + r;
        const float4* wp = reinterpret_cast<const float4*>(W_s) + (k0 << 4) + jq;
        #pragma unroll 4
        for (int k = k0; k < k1; ++k) {
            float xv = *xp; xp += XS;
            float4 w0 = wp[0];
            float4 w1 = wp[4];
            float4 w2 = wp[8];
            float4 w3 = wp[12];
            wp += 16;
            acc[0][0] += xv * w0.x; acc[0][1] += xv * w0.y;
            acc[0][2] += xv * w0.z; acc[0][3] += xv * w0.w;
            acc[1][0] += xv * w1.x; acc[1][1] += xv * w1.y;
            acc[1][2] += xv * w1.z; acc[1][3] += xv * w1.w;
            acc[2][0] += xv * w2.x; acc[2][1] += xv * w2.y;
            acc[2][2] += xv * w2.z; acc[2][3] += xv * w2.w;
            acc[3][0] += xv * w3.x; acc[3][1] += xv * w3.y;
            acc[3][2] += xv * w3.z; acc[3][3] += xv * w3.w;
        }
        {
            int hl = (r << 4) + (jq << 2);
            #pragma unroll
            for (int g = 0; g < 4; ++g) {
                float4 v = make_float4(acc[g][0], acc[g][1], acc[g][2], acc[g][3]);
                *reinterpret_cast<float4*>(zp + (split * 4 + g) * NH + hl) = v;
            }
        }
        __syncthreads();

        // ---- reduce partials, apply gates, update c/h ----
        if (tid < NH) {
            int rr = tid >> 4, jj = tid & 15;
            float z0 = b_s[jj], z1 = b_s[16 + jj], z2 = b_s[32 + jj], z3 = b_s[48 + jj];
            #pragma unroll
            for (int s = 0; s < SPLIT; ++s) {
                z0 += zp[(s * 4 + 0) * NH + tid];
                z1 += zp[(s * 4 + 1) * NH + tid];
                z2 += zp[(s * 4 + 2) * NH + tid];
                z3 += zp[(s * 4 + 3) * NH + tid];
            }
            float gi = sigm(z0);
            float gf = sigm(z1);
            float gg = tanhf(z2);
            float go = sigm(z3);
            c_state = gf * c_state + gi * gg;
            float h = go * tanhf(c_state);
            int b = rbase + rr, j = jbase + jj;
            hnext[b * HPAD + j] = h;
            if (YSEL < 2 && j < H) Y[(b * TLEN + t) * H + j] = h;
        }
        grid_sync();  // h_t complete before anyone stages step t+1
    }
}

// Final dense: out[b, o] = h_last[b, :200] @ Wd + bd.  T is even, so the final
// h lives in g_hbuf slot 0.
__global__ void dense_kernel(const float* __restrict__ Wd,
                             const float* __restrict__ bd,
                             float* __restrict__ out)
{
    int idx = blockIdx.x * blockDim.x + threadIdx.x;
    if (idx >= BSZ * 6) return;
    int b = idx / 6, o = idx - b * 6;
    const float* h = g_hbuf + b * HPAD;
    float s = bd[o];
    #pragma unroll 8
    for (int k = 0; k < 200; ++k) s += h[k] * Wd[k * 6 + o];
    out[idx] = s;
}

extern "C" void kernel_launch(void* const* d_in, const int* in_sizes, int n_in,
                              void* d_out, int out_size)
{
    const float* xs  = (const float*)d_in[0];
    const float* Wx0 = (const float*)d_in[1];
    const float* Wh0 = (const float*)d_in[2];
    const float* b0  = (const float*)d_in[3];
    const float* Wx1 = (const float*)d_in[4];
    const float* Wh1 = (const float*)d_in[5];
    const float* b1  = (const float*)d_in[6];
    const float* Wx2 = (const float*)d_in[7];
    const float* Wh2 = (const float*)d_in[8];
    const float* b2  = (const float*)d_in[9];
    const float* Wx3 = (const float*)d_in[10];
    const float* Wh3 = (const float*)d_in[11];
    const float* b3  = (const float*)d_in[12];
    const float* Wd  = (const float*)d_in[13];
    const float* bd  = (const float*)d_in[14];

    // smem bytes = (K*64 + K*(RB+1) + 64 + SPLIT*4*NH) * 4
    const size_t smem0 = (size_t)(228 * 64 + 228 * 9  + 64 + 8 * 4 * 128) * 4; //  83216
    const size_t smem1 = (size_t)(200 * 64 + 200 * 9  + 64 + 8 * 4 * 128) * 4; //  75040
    const size_t smem2 = (size_t)(300 * 64 + 300 * 17 + 64 + 4 * 4 * 256) * 4; // 113840
    const size_t smem3 = (size_t)(400 * 64 + 400 * 17 + 64 + 4 * 4 * 256) * 4; // 146240

    cudaFuncSetAttribute(lstm_layer<128, 100,  8,  8, 2, 0>,
                         cudaFuncAttributeMaxDynamicSharedMemorySize, (int)smem0);
    cudaFuncSetAttribute(lstm_layer<100, 100,  8,  8, 0, 1>,
                         cudaFuncAttributeMaxDynamicSharedMemorySize, (int)smem1);
    cudaFuncSetAttribute(lstm_layer<100, 200, 16, 16, 1, 0>,
                         cudaFuncAttributeMaxDynamicSharedMemorySize, (int)smem2);
    cudaFuncSetAttribute(lstm_layer<200, 200, 16, 16, 0, 2>,
                         cudaFuncAttributeMaxDynamicSharedMemorySize, (int)smem3);

    lstm_layer<128, 100,  8,  8, 2, 0><<<NBLK, NTHR, smem0>>>(xs,      Wx0, Wh0, b0);
    lstm_layer<100, 100,  8,  8, 0, 1><<<NBLK, NTHR, smem1>>>(nullptr, Wx1, Wh1, b1);
    lstm_layer<100, 200, 16, 16, 1, 0><<<NBLK, NTHR, smem2>>>(nullptr, Wx2, Wh2, b2);
    lstm_layer<200, 200, 16, 16, 0, 2><<<NBLK, NTHR, smem3>>>(nullptr, Wx3, Wh3, b3);
    dense_kernel<<<3, NTHR>>>(Wd, bd, (float*)d_out);
}

// round 3
// speedup vs baseline: 1.3752x; 1.3752x over previous
#include <cuda_runtime.h>

// ---------------------------------------------------------------------------
// 4-layer LSTM (B=128, T=1024, D=128, H=[100,100,200,200]) + dense head.
// R2: x@Wx+b precomputed per layer as a full-chip GEMM (no recurrence);
// persistent scan kernels only do h@Wh (K = H), 512 threads/CTA.
// ---------------------------------------------------------------------------

#define TLEN 1024
#define BSZ  128
#define HPAD 256
#define NBLK 128
#define SCAN_THR 512

// Static device scratch (no cudaMalloc allowed)
__device__ float g_zx[BSZ * TLEN * 800 + 1024];  // precomputed x@Wx+b (max 4H=800) + OOB-pad slack
__device__ float g_seq[BSZ * TLEN * 200];        // layer output sequence (input to next GEMM)
__device__ float g_hbuf[2 * BSZ * HPAD];         // per-step h double buffer
__device__ unsigned g_cnt = 0;
__device__ unsigned g_gen = 0;

__device__ __forceinline__ float sigm(float x) {
    return 1.0f / (1.0f + __expf(-x));
}

// Sense-reversing grid barrier for NBLK co-resident CTAs.
__device__ __forceinline__ void grid_sync() {
    __syncthreads();
    if (threadIdx.x == 0) {
        __threadfence();
        unsigned gen = *((volatile unsigned*)&g_gen);
        if (atomicAdd(&g_cnt, 1u) == (unsigned)(NBLK - 1)) {
            g_cnt = 0;
            __threadfence();
            atomicAdd(&g_gen, 1u);
        } else {
            while (*((volatile unsigned*)&g_gen) == gen) { __nanosleep(64); }
        }
        __threadfence();
    }
    __syncthreads();
}

// ---------------------------------------------------------------------------
// Precompute GEMM: C[M=BSZ*TLEN, N] = A[M, K] @ W[K, N] + bias.
// 128x128 CTA tile, 256 threads, 8x8 thread tile, k-chunks of 16 via smem.
// A = xs input (use_seq=false) or g_seq (use_seq=true). C = g_zx.
// ---------------------------------------------------------------------------
template <int K>
__global__ void __launch_bounds__(256, 2)
gemm_x(const float* __restrict__ Ain, const float* __restrict__ W,
       const float* __restrict__ bias, int N, int use_seq)
{
    constexpr int KC = 16;
    constexpr int NCHUNK = (K + KC - 1) / KC;

    __shared__ float A_s[KC][132];
    __shared__ float W_s[KC][132];

    const float* __restrict__ A = use_seq ? g_seq : Ain;

    const int tid = threadIdx.x;
    const int tx = tid & 15;        // n-direction (8 cols each)
    const int ty = tid >> 4;        // m-direction (8 rows each)
    const int m0 = blockIdx.y * 128;
    const int n0 = blockIdx.x * 128;

    float acc[8][8];
    #pragma unroll
    for (int i = 0; i < 8; ++i)
        #pragma unroll
        for (int j = 0; j < 8; ++j) acc[i][j] = 0.0f;

    for (int c = 0; c < NCHUNK; ++c) {
        const int k0 = c * KC;
        // stage A chunk [128 rows][KC k] -> A_s[k][row] (transposed)
        #pragma unroll
        for (int e = 0; e < 8; ++e) {
            int idx = e * 256 + tid;
            int row = idx >> 4, kk = idx & 15;
            float v = (k0 + kk < K) ? A[(size_t)(m0 + row) * K + (k0 + kk)] : 0.0f;
            A_s[kk][row] = v;
        }
        // stage W chunk [KC k][128 n]
        #pragma unroll
        for (int e = 0; e < 8; ++e) {
            int idx = e * 256 + tid;
            int kk = idx >> 7, n = idx & 127;
            float v = 0.0f;
            if ((k0 + kk < K) && (n0 + n < N)) v = W[(size_t)(k0 + kk) * N + (n0 + n)];
            W_s[kk][n] = v;
        }
        __syncthreads();
        #pragma unroll
        for (int k = 0; k < KC; ++k) {
            float a[8], w[8];
            *reinterpret_cast<float4*>(&a[0]) = *reinterpret_cast<const float4*>(&A_s[k][ty * 8]);
            *reinterpret_cast<float4*>(&a[4]) = *reinterpret_cast<const float4*>(&A_s[k][ty * 8 + 4]);
            *reinterpret_cast<float4*>(&w[0]) = *reinterpret_cast<const float4*>(&W_s[k][tx * 8]);
            *reinterpret_cast<float4*>(&w[4]) = *reinterpret_cast<const float4*>(&W_s[k][tx * 8 + 4]);
            #pragma unroll
            for (int i = 0; i < 8; ++i)
                #pragma unroll
                for (int j = 0; j < 8; ++j)
                    acc[i][j] += a[i] * w[j];
        }
        __syncthreads();
    }

    // store with bias (N % 8 == 0, so the 8-col group is fully in or out)
    if (n0 + tx * 8 < N) {
        float b[8];
        #pragma unroll
        for (int j = 0; j < 8; ++j) b[j] = bias[n0 + tx * 8 + j];
        #pragma unroll
        for (int i = 0; i < 8; ++i) {
            size_t off = (size_t)(m0 + ty * 8 + i) * N + (n0 + tx * 8);
            float4 v0 = make_float4(acc[i][0] + b[0], acc[i][1] + b[1],
                                    acc[i][2] + b[2], acc[i][3] + b[3]);
            float4 v1 = make_float4(acc[i][4] + b[4], acc[i][5] + b[5],
                                    acc[i][6] + b[6], acc[i][7] + b[7]);
            *reinterpret_cast<float4*>(&g_zx[off])     = v0;
            *reinterpret_cast<float4*>(&g_zx[off + 4]) = v1;
        }
    }
}

// ---------------------------------------------------------------------------
// Recurrent scan: z = zx[b,t] + h@Wh ; gates ; h. K = H only.
// CTA tile: RB rows x 16 j x 4 gates. 512 threads = SPLIT k-groups of RB*4.
// ---------------------------------------------------------------------------
template <int H, int RB, int CJ, int WRITE_Y>
__global__ void __launch_bounds__(SCAN_THR, 1)
lstm_scan(const float* __restrict__ Wh)
{
    constexpr int K     = H;
    constexpr int NH    = RB * 16;
    constexpr int XS    = RB + 1;
    constexpr int GSZ   = RB * 4;
    constexpr int SPLIT = SCAN_THR / GSZ;
    constexpr int N4    = 4 * H;      // zx row stride

    extern __shared__ float sm[];
    float* W_s  = sm;                 // [K][4g][16j]
    float* xh_s = W_s + K * 64;       // [K][RB] (+pad)
    float* zp   = xh_s + K * XS;      // [SPLIT][4][NH]

    const int tid   = threadIdx.x;
    const int rbase = (blockIdx.x / CJ) * RB;
    const int jbase = (blockIdx.x % CJ) * 16;

    // stationary weights (zero-padded beyond H)
    for (int idx = tid; idx < K * 64; idx += SCAN_THR) {
        int k = idx >> 6, c = idx & 63, g = c >> 4, jj = c & 15;
        int j = jbase + jj;
        W_s[idx] = (j < H) ? Wh[k * N4 + g * H + j] : 0.0f;
    }
    const int rr = tid >> 4, jj = tid & 15;
    if (tid < NH) {
        g_hbuf[(rbase + rr) * HPAD + jbase + jj] = 0.0f;
    }
    float c_state = 0.0f;
    __syncthreads();
    grid_sync();

    const int split = tid / GSZ;
    const int tg    = tid % GSZ;
    const int r     = tg >> 2;
    const int jq    = tg & 3;
    const int k0    = (split * K) / SPLIT;
    const int k1    = ((split + 1) * K) / SPLIT;

    for (int t = 0; t < TLEN; ++t) {
        const float* __restrict__ hprev = g_hbuf + (t & 1) * (BSZ * HPAD);
        float* __restrict__       hnext = g_hbuf + ((t + 1) & 1) * (BSZ * HPAD);

        // prefetch zx (hidden behind the GEMM below)
        float zx0 = 0.f, zx1 = 0.f, zx2 = 0.f, zx3 = 0.f;
        if (tid < NH) {
            const float* zrow = g_zx + ((size_t)(rbase + rr) * TLEN + t) * N4;
            int j = jbase + jj;               // may enter pad region; buffer has slack
            zx0 = zrow[0 * H + j];
            zx1 = zrow[1 * H + j];
            zx2 = zrow[2 * H + j];
            zx3 = zrow[3 * H + j];
        }

        // stage h tile [K][RB] into smem
        for (int idx = tid; idx < RB * K; idx += SCAN_THR) {
            int rr2 = idx / K;
            int k   = idx - rr2 * K;
            xh_s[k * XS + rr2] = hprev[(rbase + rr2) * HPAD + k];
        }
        __syncthreads();

        // register-tiled partial GEMM over [k0, k1)
        float acc[4][4];
        #pragma unroll
        for (int g = 0; g < 4; ++g)
            #pragma unroll
            for (int q = 0; q < 4; ++q) acc[g][q] = 0.0f;

        const float*  xp = xh_s + k0 * XS + r;
        const float4* wp = reinterpret_cast<const float4*>(W_s) + (k0 << 4) + jq;
        #pragma unroll 4
        for (int k = k0; k < k1; ++k) {
            float xv = *xp; xp += XS;
            float4 w0 = wp[0];
            float4 w1 = wp[4];
            float4 w2 = wp[8];
            float4 w3 = wp[12];
            wp += 16;
            acc[0][0] += xv * w0.x; acc[0][1] += xv * w0.y;
            acc[0][2] += xv * w0.z; acc[0][3] += xv * w0.w;
            acc[1][0] += xv * w1.x; acc[1][1] += xv * w1.y;
            acc[1][2] += xv * w1.z; acc[1][3] += xv * w1.w;
            acc[2][0] += xv * w2.x; acc[2][1] += xv * w2.y;
            acc[2][2] += xv * w2.z; acc[2][3] += xv * w2.w;
            acc[3][0] += xv * w3.x; acc[3][1] += xv * w3.y;
            acc[3][2] += xv * w3.z; acc[3][3] += xv * w3.w;
        }
        {
            int hl = (r << 4) + (jq << 2);
            #pragma unroll
            for (int g = 0; g < 4; ++g) {
                float4 v = make_float4(acc[g][0], acc[g][1], acc[g][2], acc[g][3]);
                *reinterpret_cast<float4*>(zp + (split * 4 + g) * NH + hl) = v;
            }
        }
        __syncthreads();

        // reduce partials + zx, gates, update c/h
        if (tid < NH) {
            float z0 = zx0, z1 = zx1, z2 = zx2, z3 = zx3;
            #pragma unroll
            for (int s = 0; s < SPLIT; ++s) {
                z0 += zp[(s * 4 + 0) * NH + tid];
                z1 += zp[(s * 4 + 1) * NH + tid];
                z2 += zp[(s * 4 + 2) * NH + tid];
                z3 += zp[(s * 4 + 3) * NH + tid];
            }
            float gi = sigm(z0);
            float gf = sigm(z1);
            float gg = tanhf(z2);
            float go = sigm(z3);
            c_state = gf * c_state + gi * gg;
            float h = go * tanhf(c_state);
            int b = rbase + rr, j = jbase + jj;
            hnext[b * HPAD + j] = h;
            if (WRITE_Y && j < H) g_seq[((size_t)b * TLEN + t) * H + j] = h;
        }
        grid_sync();  // h_t complete before anyone stages step t+1
    }
}

// Final dense: out[b, o] = h_last[b, :200] @ Wd + bd. TLEN even -> slot 0.
__global__ void dense_kernel(const float* __restrict__ Wd,
                             const float* __restrict__ bd,
                             float* __restrict__ out)
{
    int idx = blockIdx.x * blockDim.x + threadIdx.x;
    if (idx >= BSZ * 6) return;
    int b = idx / 6, o = idx - b * 6;
    const float* h = g_hbuf + b * HPAD;
    float s = bd[o];
    #pragma unroll 8
    for (int k = 0; k < 200; ++k) s += h[k] * Wd[k * 6 + o];
    out[idx] = s;
}

extern "C" void kernel_launch(void* const* d_in, const int* in_sizes, int n_in,
                              void* d_out, int out_size)
{
    const float* xs  = (const float*)d_in[0];
    const float* Wx0 = (const float*)d_in[1];
    const float* Wh0 = (const float*)d_in[2];
    const float* b0  = (const float*)d_in[3];
    const float* Wx1 = (const float*)d_in[4];
    const float* Wh1 = (const float*)d_in[5];
    const float* b1  = (const float*)d_in[6];
    const float* Wx2 = (const float*)d_in[7];
    const float* Wh2 = (const float*)d_in[8];
    const float* b2  = (const float*)d_in[9];
    const float* Wx3 = (const float*)d_in[10];
    const float* Wh3 = (const float*)d_in[11];
    const float* b3  = (const float*)d_in[12];
    const float* Wd  = (const float*)d_in[13];
    const float* bd  = (const float*)d_in[14];

    // scan smem: (K*64 + K*(RB+1) + SPLIT*4*NH) * 4 bytes
    const size_t smem_s = (size_t)(100 * 64 + 100 * 9  + 16 * 4 * 128) * 4; // 61968
    const size_t smem_l = (size_t)(200 * 64 + 200 * 17 +  8 * 4 * 256) * 4; // 97568

    cudaFuncSetAttribute(lstm_scan<100,  8,  8, 1>,
                         cudaFuncAttributeMaxDynamicSharedMemorySize, (int)smem_s);
    cudaFuncSetAttribute(lstm_scan<200, 16, 16, 1>,
                         cudaFuncAttributeMaxDynamicSharedMemorySize, (int)smem_l);
    cudaFuncSetAttribute(lstm_scan<200, 16, 16, 0>,
                         cudaFuncAttributeMaxDynamicSharedMemorySize, (int)smem_l);

    const dim3 gN400(4, 1024);   // ceil(400/128) x (131072/128)
    const dim3 gN800(7, 1024);   // ceil(800/128)

    // L0
    gemm_x<128><<<gN400, 256>>>(xs, Wx0, b0, 400, 0);
    lstm_scan<100,  8,  8, 1><<<NBLK, SCAN_THR, smem_s>>>(Wh0);
    // L1
    gemm_x<100><<<gN400, 256>>>(nullptr, Wx1, b1, 400, 1);
    lstm_scan<100,  8,  8, 1><<<NBLK, SCAN_THR, smem_s>>>(Wh1);
    // L2
    gemm_x<100><<<gN800, 256>>>(nullptr, Wx2, b2, 800, 1);
    lstm_scan<200, 16, 16, 1><<<NBLK, SCAN_THR, smem_l>>>(Wh2);
    // L3
    gemm_x<200><<<gN800, 256>>>(nullptr, Wx3, b3, 800, 1);
    lstm_scan<200, 16, 16, 0><<<NBLK, SCAN_THR, smem_l>>>(Wh3);
    // head
    dense_kernel<<<3, 256>>>(Wd, bd, (float*)d_out);
}

// round 4
// speedup vs baseline: 4.0170x; 2.9210x over previous
#include <cuda_runtime.h>
#include <cstdint>

// ---------------------------------------------------------------------------
// 4-layer LSTM (B=128, T=1024, D=128, H=[100,100,200,200]) + dense head.
// R3: batch-parallel recurrence, NO grid barriers.
//   - x@Wx+b precomputed per layer as full-chip fp32 GEMM (as R2).
//   - H=100 scan: 1 CTA per batch row, Wh in registers, h in SMEM.
//   - H=200 scan: cluster of 4 CTAs (j-sliced Wh in registers), h exchanged
//     via DSMEM + barrier.cluster per step.
// ---------------------------------------------------------------------------

#define TLEN 1024
#define BSZ  128
#define HPAD 256

__device__ float g_zx[(size_t)BSZ * TLEN * 800];  // precomputed x@Wx+b
__device__ float g_seq[(size_t)BSZ * TLEN * 200]; // layer output sequence
__device__ float g_hbuf[BSZ * HPAD];              // final h for dense head

__device__ __forceinline__ float sigm(float x) {
    return 1.0f / (1.0f + __expf(-x));
}

// ---------------------------------------------------------------------------
// Precompute GEMM: C[M=BSZ*TLEN, N] = A[M, K] @ W[K, N] + bias -> g_zx.
// 128x128 CTA tile, 256 threads, 8x8 thread tile, k-chunks of 16 via smem.
// ---------------------------------------------------------------------------
template <int K>
__global__ void __launch_bounds__(256, 2)
gemm_x(const float* __restrict__ Ain, const float* __restrict__ W,
       const float* __restrict__ bias, int N, int use_seq)
{
    constexpr int KC = 16;
    constexpr int NCHUNK = (K + KC - 1) / KC;

    __shared__ float A_s[KC][132];
    __shared__ float W_s[KC][132];

    const float* __restrict__ A = use_seq ? g_seq : Ain;

    const int tid = threadIdx.x;
    const int tx = tid & 15;
    const int ty = tid >> 4;
    const int m0 = blockIdx.y * 128;
    const int n0 = blockIdx.x * 128;

    float acc[8][8];
    #pragma unroll
    for (int i = 0; i < 8; ++i)
        #pragma unroll
        for (int j = 0; j < 8; ++j) acc[i][j] = 0.0f;

    for (int c = 0; c < NCHUNK; ++c) {
        const int k0 = c * KC;
        #pragma unroll
        for (int e = 0; e < 8; ++e) {
            int idx = e * 256 + tid;
            int row = idx >> 4, kk = idx & 15;
            A_s[kk][row] = (k0 + kk < K) ? A[(size_t)(m0 + row) * K + (k0 + kk)] : 0.0f;
        }
        #pragma unroll
        for (int e = 0; e < 8; ++e) {
            int idx = e * 256 + tid;
            int kk = idx >> 7, n = idx & 127;
            float v = 0.0f;
            if ((k0 + kk < K) && (n0 + n < N)) v = W[(size_t)(k0 + kk) * N + (n0 + n)];
            W_s[kk][n] = v;
        }
        __syncthreads();
        #pragma unroll
        for (int k = 0; k < KC; ++k) {
            float a[8], w[8];
            *reinterpret_cast<float4*>(&a[0]) = *reinterpret_cast<const float4*>(&A_s[k][ty * 8]);
            *reinterpret_cast<float4*>(&a[4]) = *reinterpret_cast<const float4*>(&A_s[k][ty * 8 + 4]);
            *reinterpret_cast<float4*>(&w[0]) = *reinterpret_cast<const float4*>(&W_s[k][tx * 8]);
            *reinterpret_cast<float4*>(&w[4]) = *reinterpret_cast<const float4*>(&W_s[k][tx * 8 + 4]);
            #pragma unroll
            for (int i = 0; i < 8; ++i)
                #pragma unroll
                for (int j = 0; j < 8; ++j)
                    acc[i][j] += a[i] * w[j];
        }
        __syncthreads();
    }

    if (n0 + tx * 8 < N) {
        float b[8];
        #pragma unroll
        for (int j = 0; j < 8; ++j) b[j] = bias[n0 + tx * 8 + j];
        #pragma unroll
        for (int i = 0; i < 8; ++i) {
            size_t off = (size_t)(m0 + ty * 8 + i) * N + (n0 + tx * 8);
            float4 v0 = make_float4(acc[i][0] + b[0], acc[i][1] + b[1],
                                    acc[i][2] + b[2], acc[i][3] + b[3]);
            float4 v1 = make_float4(acc[i][4] + b[4], acc[i][5] + b[5],
                                    acc[i][6] + b[6], acc[i][7] + b[7]);
            *reinterpret_cast<float4*>(&g_zx[off])     = v0;
            *reinterpret_cast<float4*>(&g_zx[off + 4]) = v1;
        }
    }
}

// ---------------------------------------------------------------------------
// H=100 scan: 1 CTA per batch row. Wh in registers: thread (s=tid/100,
// j=tid%100) holds W[k=s*20..+20][4 gates] for column j. h in SMEM only.
// ---------------------------------------------------------------------------
__global__ void __launch_bounds__(512, 1)
scan100(const float* __restrict__ Wh)
{
    __shared__ float h_s[112];
    __shared__ float zp[5][4][100];

    const int tid = threadIdx.x;
    const int b   = blockIdx.x;
    const int s   = tid / 100;          // 0..4 active, 5 = idle tail
    const int j   = tid % 100;
    const bool gemm_act = (tid < 500);
    const bool red_act  = (tid < 100);

    float w[20][4];
    if (gemm_act) {
        #pragma unroll
        for (int kk = 0; kk < 20; ++kk) {
            const int k = s * 20 + kk;
            #pragma unroll
            for (int g = 0; g < 4; ++g)
                w[kk][g] = Wh[k * 400 + g * 100 + j];
        }
    }
    if (red_act) h_s[j] = 0.0f;
    float c = 0.0f;
    __syncthreads();

    const float* __restrict__ zbase = g_zx + (size_t)b * TLEN * 400;
    float* __restrict__ ybase = g_seq + (size_t)b * TLEN * 100;

    for (int t = 0; t < TLEN; ++t) {
        float zx0 = 0.f, zx1 = 0.f, zx2 = 0.f, zx3 = 0.f;
        if (red_act) {
            const float* zr = zbase + (size_t)t * 400;
            zx0 = zr[j]; zx1 = zr[100 + j]; zx2 = zr[200 + j]; zx3 = zr[300 + j];
        }
        if (gemm_act) {
            float a0 = 0.f, a1 = 0.f, a2 = 0.f, a3 = 0.f;
            const int k0 = s * 20;
            #pragma unroll
            for (int kk = 0; kk < 20; ++kk) {
                float xv = h_s[k0 + kk];
                a0 += xv * w[kk][0];
                a1 += xv * w[kk][1];
                a2 += xv * w[kk][2];
                a3 += xv * w[kk][3];
            }
            zp[s][0][j] = a0; zp[s][1][j] = a1;
            zp[s][2][j] = a2; zp[s][3][j] = a3;
        }
        __syncthreads();
        if (red_act) {
            float z0 = zx0, z1 = zx1, z2 = zx2, z3 = zx3;
            #pragma unroll
            for (int ss = 0; ss < 5; ++ss) {
                z0 += zp[ss][0][j]; z1 += zp[ss][1][j];
                z2 += zp[ss][2][j]; z3 += zp[ss][3][j];
            }
            float gi = sigm(z0), gf = sigm(z1), gg = tanhf(z2), go = sigm(z3);
            c = gf * c + gi * gg;
            float h = go * tanhf(c);
            h_s[j] = h;
            ybase[(size_t)t * 100 + j] = h;
        }
        __syncthreads();
    }
}

// ---------------------------------------------------------------------------
// H=200 scan: cluster of 4 CTAs; CTA rank r owns j-slice [50r, 50r+50),
// cluster owns 4 batch rows. Wh slice in registers; h exchanged via DSMEM.
// ---------------------------------------------------------------------------
template <int WRITE_Y>
__global__ void __launch_bounds__(512, 1) __cluster_dims__(4, 1, 1)
scan200(const float* __restrict__ Wh)
{
    __shared__ float h_s[2][200 * 4];     // [buf][jglobal][row]
    __shared__ float zp[10][4][4][52];    // [split][row][gate][jl]

    const int tid = threadIdx.x;
    uint32_t rank;
    asm("mov.u32 %0, %%cluster_ctarank;" : "=r"(rank));
    const int cl = blockIdx.x >> 2;

    const int s  = tid / 50;              // gemm: split 0..9 (tid<500)
    const int jl = tid % 50;
    const bool gemm_act = (tid < 500);
    const bool red_act  = (tid < 200);    // reduce: row = tid/50 (0..3)
    const int  rr = s;                    // row for reduce role
    const int  jg = (int)rank * 50 + jl;  // global j column

    uint32_t hs_addr;
    {
        const void* p = (const void*)&h_s[0][0];
        asm("{ .reg .u64 t; cvta.to.shared.u64 t, %1; cvt.u32.u64 %0, t; }"
            : "=r"(hs_addr) : "l"(p));
    }

    // register-resident Wh slice: thread (s, jl) holds k=s*20..+20, 4 gates, col jg
    float w[20][4];
    if (gemm_act) {
        #pragma unroll
        for (int kk = 0; kk < 20; ++kk) {
            const int k = s * 20 + kk;
            #pragma unroll
            for (int g = 0; g < 4; ++g)
                w[kk][g] = Wh[k * 800 + g * 200 + jg];
        }
    }
    // zero both h buffers
    for (int i = tid; i < 2 * 800; i += 512) h_s[0][i] = 0.0f;
    float c = 0.0f;
    __syncthreads();
    asm volatile("barrier.cluster.arrive.aligned;" ::: "memory");
    asm volatile("barrier.cluster.wait.aligned;" ::: "memory");

    const int b = cl * 4 + rr;            // batch row for reduce role
    const float* __restrict__ zbase = g_zx + (size_t)b * TLEN * 800;
    float* __restrict__ ybase = g_seq + (size_t)b * TLEN * 200;

    for (int t = 0; t < TLEN; ++t) {
        const int cur = t & 1, nxt = cur ^ 1;

        float zx0 = 0.f, zx1 = 0.f, zx2 = 0.f, zx3 = 0.f;
        if (red_act) {
            const float* zr = zbase + (size_t)t * 800;
            zx0 = zr[jg]; zx1 = zr[200 + jg]; zx2 = zr[400 + jg]; zx3 = zr[600 + jg];
        }

        if (gemm_act) {
            float acc[4][4];
            #pragma unroll
            for (int r2 = 0; r2 < 4; ++r2)
                #pragma unroll
                for (int g = 0; g < 4; ++g) acc[r2][g] = 0.0f;

            const float4* hp = reinterpret_cast<const float4*>(h_s[cur]);
            const int k0 = s * 20;
            #pragma unroll
            for (int kk = 0; kk < 20; ++kk) {
                float4 xv = hp[k0 + kk];
                #pragma unroll
                for (int g = 0; g < 4; ++g) {
                    acc[0][g] += xv.x * w[kk][g];
                    acc[1][g] += xv.y * w[kk][g];
                    acc[2][g] += xv.z * w[kk][g];
                    acc[3][g] += xv.w * w[kk][g];
                }
            }
            #pragma unroll
            for (int r2 = 0; r2 < 4; ++r2)
                #pragma unroll
                for (int g = 0; g < 4; ++g)
                    zp[s][r2][g][jl] = acc[r2][g];
        }
        __syncthreads();

        if (red_act) {
            float z0 = zx0, z1 = zx1, z2 = zx2, z3 = zx3;
            #pragma unroll
            for (int ss = 0; ss < 10; ++ss) {
                z0 += zp[ss][rr][0][jl];
                z1 += zp[ss][rr][1][jl];
                z2 += zp[ss][rr][2][jl];
                z3 += zp[ss][rr][3][jl];
            }
            float gi = sigm(z0), gf = sigm(z1), gg = tanhf(z2), go = sigm(z3);
            c = gf * c + gi * gg;
            float h = go * tanhf(c);

            // broadcast h to h_s[nxt][jg][rr] in all 4 cluster CTAs
            uint32_t laddr = hs_addr + (uint32_t)(nxt * 800 + jg * 4 + rr) * 4u;
            #pragma unroll
            for (int p = 0; p < 4; ++p) {
                uint32_t raddr;
                asm("mapa.shared::cluster.u32 %0, %1, %2;"
                    : "=r"(raddr) : "r"(laddr), "r"(p));
                asm volatile("st.shared::cluster.f32 [%0], %1;"
                             :: "r"(raddr), "f"(h) : "memory");
            }
            if (WRITE_Y) ybase[(size_t)t * 200 + jg] = h;
            if (t == TLEN - 1) g_hbuf[b * HPAD + jg] = h;
        }
        // cluster barrier: release our h writes, acquire peers'
        asm volatile("barrier.cluster.arrive.aligned;" ::: "memory");
        asm volatile("barrier.cluster.wait.aligned;" ::: "memory");
    }
}

// Final dense: out[b, o] = h_last[b, :200] @ Wd + bd.
__global__ void dense_kernel(const float* __restrict__ Wd,
                             const float* __restrict__ bd,
                             float* __restrict__ out)
{
    int idx = blockIdx.x * blockDim.x + threadIdx.x;
    if (idx >= BSZ * 6) return;
    int b = idx / 6, o = idx - b * 6;
    const float* h = g_hbuf + b * HPAD;
    float s = bd[o];
    #pragma unroll 8
    for (int k = 0; k < 200; ++k) s += h[k] * Wd[k * 6 + o];
    out[idx] = s;
}

extern "C" void kernel_launch(void* const* d_in, const int* in_sizes, int n_in,
                              void* d_out, int out_size)
{
    const float* xs  = (const float*)d_in[0];
    const float* Wx0 = (const float*)d_in[1];
    const float* Wh0 = (const float*)d_in[2];
    const float* b0  = (const float*)d_in[3];
    const float* Wx1 = (const float*)d_in[4];
    const float* Wh1 = (const float*)d_in[5];
    const float* b1  = (const float*)d_in[6];
    const float* Wx2 = (const float*)d_in[7];
    const float* Wh2 = (const float*)d_in[8];
    const float* b2  = (const float*)d_in[9];
    const float* Wx3 = (const float*)d_in[10];
    const float* Wh3 = (const float*)d_in[11];
    const float* b3  = (const float*)d_in[12];
    const float* Wd  = (const float*)d_in[13];
    const float* bd  = (const float*)d_in[14];

    const dim3 gN400(4, 1024);   // ceil(400/128) x (131072/128)
    const dim3 gN800(7, 1024);   // ceil(800/128)

    // L0
    gemm_x<128><<<gN400, 256>>>(xs, Wx0, b0, 400, 0);
    scan100<<<BSZ, 512>>>(Wh0);
    // L1
    gemm_x<100><<<gN400, 256>>>(nullptr, Wx1, b1, 400, 1);
    scan100<<<BSZ, 512>>>(Wh1);
    // L2
    gemm_x<100><<<gN800, 256>>>(nullptr, Wx2, b2, 800, 1);
    scan200<1><<<BSZ, 512>>>(Wh2);
    // L3
    gemm_x<200><<<gN800, 256>>>(nullptr, Wx3, b3, 800, 1);
    scan200<0><<<BSZ, 512>>>(Wh3);
    // head
    dense_kernel<<<3, 256>>>(Wd, bd, (float*)d_out);
}